// round 14
// baseline (speedup 1.0000x reference)
#include <cuda_runtime.h>
#include <cuda_bf16.h>
#include <math.h>

#define Bsz 1024
#define Tt  100
#define Fd  64
#define Hd  256
#define KT  384            // gates K: 64 (c_c) + 64 (m) + 256 (h)
#define KPP 200            // padded k-pairs (192 used + 8 pad for prefetch)
#define NCTA 128
#define NTH  512
#define PREF 8             // prefetch depth in k-pairs (16 k lookahead)
#define TF   (Tt*Fd)
#define BTF  (Bsz*Tt*Fd)

// uint2 at [(kp*2+half)*256 + jj]: .x = k=2kp, .y = k=2kp+1
// each uint = bf16x2(gateA, gateB); half0 -> (i,f), half1 -> (g,o)
static __device__ uint2 g_W2[KPP * 2 * 256];
static __device__ float g_part[Tt * NCTA * 4];

typedef unsigned long long u64;

__device__ __forceinline__ u64 pk2(float lo, float hi) {
    u64 r; asm("mov.b64 %0,{%1,%2};" : "=l"(r) : "f"(lo), "f"(hi)); return r;
}
__device__ __forceinline__ void upk2(u64 v, float& lo, float& hi) {
    asm("mov.b64 {%0,%1},%2;" : "=f"(lo), "=f"(hi) : "l"(v));
}
__device__ __forceinline__ u64 dup2(float w) {
    u64 r; asm("mov.b64 %0,{%1,%1};" : "=l"(r) : "f"(w)); return r;
}
__device__ __forceinline__ u64 ffma2(u64 a, u64 b, u64 c) {
    u64 d; asm("fma.rn.f32x2 %0,%1,%2,%3;" : "=l"(d) : "l"(a), "l"(b), "l"(c)); return d;
}
__device__ __forceinline__ u64 add2(u64 a, u64 b) {
    u64 d; asm("add.rn.f32x2 %0,%1,%2;" : "=l"(d) : "l"(a), "l"(b)); return d;
}
// sigmoid(x) = 0.5*tanh(0.5x)+0.5 using HW tanh (1 MUFU, no divide)
__device__ __forceinline__ float sigm(float x) {
    float y; asm("tanh.approx.f32 %0, %1;" : "=f"(y) : "f"(0.5f * x));
    return fmaf(0.5f, y, 0.5f);
}
// precise-ish tanh for g/c path (exp-based)
__device__ __forceinline__ float ftanh(float x) {
    x = fminf(fmaxf(x, -15.0f), 15.0f);
    const float e = __expf(2.0f * x);
    return __fdividef(e - 1.0f, e + 1.0f);
}

// SMEM layout (bytes)
#define OFF_VP     0        // u64[384][4]  v = [c_c | m | h], interleaved [k][rp]
#define OFF_CP     12288    // u64[4][256]  LSTM cell state
#define OFF_DP     20480    // u64[4][64]   deltas; reused as alpha-preact after P2
#define OFF_GX     22528    // u64[4][64]   gamma_x
#define OFF_XC     24576    // u64[4][64]   x_c
#define OFF_GS     26624    // u64[8][256]: [0..3]=i/f preacts for rp2,3 ; [4..7]=g/o for rp0,1
#define OFF_H2     43008    // u64[4][256]  h duplicate, [rp][j] contiguous
#define OFF_WDH    51200    // float[64][256]   W_dh^T  [k][j]
#define OFF_WHP    116736   // float2[128][64]  W_hist pairs: [j/2][f] = (W[j],W[j+1])
#define OFF_WFP    182272   // float2[32][64]   W_feat pairs: [k/2][f]
#define OFF_WCP    198656   // uint[64][64]     W_comb bf16x2: [k][f] = (W[f][k], W[f][64+k])
#define OFF_BDH    215040   // float[256]
#define OFF_SM     216064   // float[320]: bdx|bhist|bfeat|bcomb|wdx_diag
#define OFF_RED    217344   // float[8][4]
#define SMEM_BYTES 217472

// ---------------------------------------------------------------------------
// Prep: pack fused transposed gate weights to bf16 pairs, k-paired layout.
// ---------------------------------------------------------------------------
__global__ void rits_prep(const float* __restrict__ Wih, const float* __restrict__ Whh) {
    const int k = blockIdx.x;          // 0..2*KPP-1
    const int j = threadIdx.x;
    float w[4];
    #pragma unroll
    for (int ty = 0; ty < 4; ++ty) {
        float v = 0.0f;
        if (k < KT)
            v = (k < 128) ? Wih[(ty * 256 + j) * 128 + k]
                          : Whh[(ty * 256 + j) * 256 + (k - 128)];
        w[ty] = v;
    }
    __nv_bfloat162 p0 = __floats2bfloat162_rn(w[0], w[1]);   // i (lo), f (hi)
    __nv_bfloat162 p1 = __floats2bfloat162_rn(w[2], w[3]);   // g (lo), o (hi)
    unsigned int* base = (unsigned int*)g_W2;
    const int kp = k >> 1, sub = k & 1;
    base[(((kp * 2 + 0) * 256) + j) * 2 + sub] = *(unsigned int*)&p0;
    base[(((kp * 2 + 1) * 256) + j) * 2 + sub] = *(unsigned int*)&p1;
}

// ---------------------------------------------------------------------------
// Main persistent kernel: 128 CTAs x 8 rows x 100 steps, no grid sync.
// ---------------------------------------------------------------------------
__global__ void __launch_bounds__(NTH, 1)
rits_main(const float* __restrict__ X,   const float* __restrict__ MM,
          const float* __restrict__ DD,
          const float* __restrict__ Wdh, const float* __restrict__ bdh,
          const float* __restrict__ Wdx, const float* __restrict__ bdx,
          const float* __restrict__ Whist, const float* __restrict__ bhist,
          const float* __restrict__ Wfeat, const float* __restrict__ bfeat,
          const float* __restrict__ Wcomb, const float* __restrict__ bcomb,
          const float* __restrict__ bih, const float* __restrict__ bhh,
          float* __restrict__ out)
{
    extern __shared__ char sm[];
    u64*    vpsh   = (u64*)(sm + OFF_VP);     // [k][rp]
    u64*    cpsh   = (u64*)(sm + OFF_CP);     // [rp][j]
    u64*    dpsh   = (u64*)(sm + OFF_DP);     // [rp][f]; later alpha-preact
    u64*    gxsh   = (u64*)(sm + OFF_GX);     // [rp][f]
    u64*    xcsh   = (u64*)(sm + OFF_XC);     // [rp][f]
    u64*    gsh    = (u64*)(sm + OFF_GS);     // exchange regions (see layout)
    u64*    hsh2   = (u64*)(sm + OFF_H2);     // [rp][j]
    float*  sWdhT  = (float*)(sm + OFF_WDH);
    float2* sWhP   = (float2*)(sm + OFF_WHP);
    float2* sWfP   = (float2*)(sm + OFF_WFP);
    unsigned int* sWcP = (unsigned int*)(sm + OFF_WCP);
    float*  sbdh   = (float*)(sm + OFF_BDH);
    float*  ssm    = (float*)(sm + OFF_SM);
    float*  red    = (float*)(sm + OFF_RED);

    const int tid  = threadIdx.x;
    const int bid  = blockIdx.x;
    const int f_   = tid & 63;
    const int rp_  = (tid >> 6) & 3;
    const int wid  = tid >> 5;
    const int lane = tid & 31;
    const int jj   = tid & 255;
    const int half = tid >> 8;              // 0: gates i,f ; 1: gates g,o

    // ---- one-time weight staging ----
    for (int idx = tid; idx < Hd * Fd; idx += NTH) {        // W_dh [H][F] -> [k][j]
        int j = idx / Fd, k = idx % Fd;
        sWdhT[k * Hd + j] = Wdh[idx];
    }
    for (int idx = tid; idx < Fd * Hd; idx += NTH) {        // W_hist [F][H] -> pairs [j/2][f]
        int f = idx / Hd, j = idx % Hd;
        ((float*)sWhP)[((j >> 1) * 64 + f) * 2 + (j & 1)] = Whist[idx];
    }
    for (int idx = tid; idx < Fd * Fd; idx += NTH) {        // W_feat masked -> pairs [k/2][f]
        int f = idx / Fd, k = idx % Fd;
        ((float*)sWfP)[((k >> 1) * 64 + f) * 2 + (k & 1)] = (f == k) ? 0.0f : Wfeat[idx];
    }
    for (int idx = tid; idx < 64 * 64; idx += NTH) {        // W_comb -> bf16x2 [k][f]
        int f = idx >> 6, k = idx & 63;
        __nv_bfloat162 p = __floats2bfloat162_rn(Wcomb[f * 128 + k], Wcomb[f * 128 + 64 + k]);
        sWcP[k * 64 + f] = *(unsigned int*)&p;
    }
    for (int idx = tid; idx < Hd; idx += NTH) sbdh[idx] = bdh[idx];
    for (int idx = tid; idx < Fd; idx += NTH) {
        ssm[idx]       = bdx[idx];
        ssm[64 + idx]  = bhist[idx];
        ssm[128 + idx] = bfeat[idx];
        ssm[192 + idx] = bcomb[idx];
        ssm[256 + idx] = Wdx[idx * Fd + idx];
    }
    for (int idx = tid; idx < KT * 4; idx += NTH) vpsh[idx] = 0ULL;
    for (int idx = tid; idx < 4 * Hd; idx += NTH) { cpsh[idx] = 0ULL; hsh2[idx] = 0ULL; }
    __syncthreads();

    const float my_bdh   = sbdh[jj];
    const float my_bdx   = ssm[f_];
    const float my_bhist = ssm[64 + f_];
    const float my_bfeat = ssm[128 + f_];
    const float my_bcomb = ssm[192 + f_];
    const float my_wdx   = ssm[256 + f_];
    const float bga = bih[(half * 2 + 0) * 256 + jj] + bhh[(half * 2 + 0) * 256 + jj];
    const float bgb = bih[(half * 2 + 1) * 256 + jj] + bhh[(half * 2 + 1) * 256 + jj];

    long base0 = ((long)(bid * 8 + rp_ * 2)) * TF + f_;   // row-pair base (tid<256 active)
    float x0 = 0, x1 = 0, m0 = 0, m1 = 0;

    // ---------- prologue P0 (t=0) ----------
    if (tid < 256) {
        x0 = X[base0];  x1 = X[base0 + TF];
        m0 = MM[base0]; m1 = MM[base0 + TF];
        const float d0 = DD[base0], d1 = DD[base0 + TF];
        dpsh[rp_ * 64 + f_] = pk2(d0, d1);
        vpsh[(64 + f_) * 4 + rp_] = pk2(m0, m1);
        const float g0 = __expf(-fmaxf(fmaf(d0, my_wdx, my_bdx), 0.0f));
        const float g1 = __expf(-fmaxf(fmaf(d1, my_wdx, my_bdx), 0.0f));
        gxsh[rp_ * 64 + f_] = pk2(g0, g1);
    }
    __syncthreads();

    const uint2* wp = g_W2 + half * 256 + jj;   // stride 512 uint2 per k-pair

    for (int t = 0; t < Tt; ++t) {
        // ---- prefetch gate-weight pipeline (static data; overlaps P1-P3) ----
        uint2 buf[PREF];
        #pragma unroll
        for (int p = 0; p < PREF; ++p) buf[p] = wp[p * 512];

        // ---------- phase 1 (all 512): gamma_h, h *= gamma_h ----------
        {
            const int rb = half * 2;
            u64 a0 = 0ULL, a1 = 0ULL, a2 = 0ULL, a3 = 0ULL;
            #pragma unroll 8
            for (int k = 0; k < Fd; k += 2) {
                const u64 w0 = dup2(sWdhT[k * Hd + jj]);
                const u64 w1 = dup2(sWdhT[(k + 1) * Hd + jj]);
                const ulonglong2 dA = *(const ulonglong2*)(dpsh + rb * 64 + k);
                const ulonglong2 dB = *(const ulonglong2*)(dpsh + (rb + 1) * 64 + k);
                a0 = ffma2(dA.x, w0, a0);  a1 = ffma2(dA.y, w1, a1);
                a2 = ffma2(dB.x, w0, a2);  a3 = ffma2(dB.y, w1, a3);
            }
            const u64 sA = add2(a0, a1), sB = add2(a2, a3);
            float l0, h0v, l1, h1v;
            upk2(sA, l0, h0v);
            upk2(sB, l1, h1v);
            const float ga = __expf(-fmaxf(l0  + my_bdh, 0.0f));
            const float gb = __expf(-fmaxf(h0v + my_bdh, 0.0f));
            const float gc = __expf(-fmaxf(l1  + my_bdh, 0.0f));
            const float gd = __expf(-fmaxf(h1v + my_bdh, 0.0f));
            ulonglong2* hp = (ulonglong2*)(vpsh + (128 + jj) * 4 + rb);
            ulonglong2 hv = *hp;
            float ha, hb, hc, hd;
            upk2(hv.x, ha, hb);  upk2(hv.y, hc, hd);
            hv.x = pk2(ha * ga, hb * gb);
            hv.y = pk2(hc * gc, hd * gd);
            *hp = hv;
            hsh2[rb * 256 + jj]       = hv.x;
            hsh2[(rb + 1) * 256 + jj] = hv.y;
        }
        __syncthreads();

        // ---------- phase 2: half0 -> x_h GEMV; half1 -> alpha GEMV ----------
        float xh0 = 0, xh1 = 0, s1 = 0;
        if (half == 0) {
            u64 acc0 = dup2(my_bhist), acc1 = 0ULL, acc2 = 0ULL, acc3 = 0ULL;
            #pragma unroll 8
            for (int jp = 0; jp < 128; jp += 2) {
                const ulonglong2 vA = *(const ulonglong2*)(hsh2 + rp_ * 256 + 2 * jp);
                const float2 wA = sWhP[jp * 64 + f_];
                const ulonglong2 vB = *(const ulonglong2*)(hsh2 + rp_ * 256 + 2 * jp + 2);
                const float2 wB = sWhP[(jp + 1) * 64 + f_];
                acc0 = ffma2(vA.x, dup2(wA.x), acc0);
                acc1 = ffma2(vA.y, dup2(wA.y), acc1);
                acc2 = ffma2(vB.x, dup2(wB.x), acc2);
                acc3 = ffma2(vB.y, dup2(wB.y), acc3);
            }
            const u64 acc = add2(add2(acc0, acc1), add2(acc2, acc3));
            upk2(acc, xh0, xh1);
            const float xc0 = m0 * x0 + (1.0f - m0) * xh0;
            const float xc1 = m1 * x1 + (1.0f - m1) * xh1;
            xcsh[rp_ * 64 + f_] = pk2(xc0, xc1);
            s1 = fabsf(xh0 - x0) * m0 + fabsf(xh1 - x1) * m1;
        } else {
            // alpha preact = [gamma_x, m] @ W_comb^T + b  (bf16 packed weights)
            u64 a0a = dup2(my_bcomb), a1a = 0ULL, a2a = 0ULL, a3a = 0ULL;
            #pragma unroll 8
            for (int kp = 0; kp < 32; ++kp) {
                const ulonglong2 g2 = *(const ulonglong2*)(gxsh + rp_ * 64 + 2 * kp);
                const unsigned int u0 = sWcP[(2 * kp) * 64 + f_];
                const unsigned int u1 = sWcP[(2 * kp + 1) * 64 + f_];
                a0a = ffma2(g2.x, dup2(__uint_as_float(u0 << 16)), a0a);
                a1a = ffma2(g2.y, dup2(__uint_as_float(u1 << 16)), a1a);
                a2a = ffma2(vpsh[(64 + 2 * kp) * 4 + rp_],
                            dup2(__uint_as_float(u0 & 0xffff0000u)), a2a);
                a3a = ffma2(vpsh[(64 + 2 * kp + 1) * 4 + rp_],
                            dup2(__uint_as_float(u1 & 0xffff0000u)), a3a);
            }
            dpsh[rp_ * 64 + f_] = add2(add2(a0a, a1a), add2(a2a, a3a));
        }
        __syncthreads();

        // ---------- phase 3 (tid<256): z_h, c_h, c_c, out, losses ----------
        if (tid < 256) {
            u64 z0a = dup2(my_bfeat), z1a = 0ULL;
            #pragma unroll 8
            for (int kp = 0; kp < 32; ++kp) {
                const ulonglong2 xv = *(const ulonglong2*)(xcsh + rp_ * 64 + 2 * kp);
                const float2 w2 = sWfP[kp * 64 + f_];
                z0a = ffma2(xv.x, dup2(w2.x), z0a);
                z1a = ffma2(xv.y, dup2(w2.y), z1a);
            }
            float z0, z1, al0, al1;
            upk2(add2(z0a, z1a), z0, z1);
            upk2(dpsh[rp_ * 64 + f_], al0, al1);
            al0 = sigm(al0); al1 = sigm(al1);
            const float ch0 = al0 * z0 + (1.0f - al0) * xh0;
            const float ch1 = al1 * z1 + (1.0f - al1) * xh1;
            float s2 = fabsf(z0 - x0) * m0 + fabsf(z1 - x1) * m1;
            float s3 = fabsf(ch0 - x0) * m0 + fabsf(ch1 - x1) * m1;
            float sd = m0 + m1;
            const float cc0 = m0 * x0 + (1.0f - m0) * ch0;    // imputed element
            const float cc1 = m1 * x1 + (1.0f - m1) * ch1;
            vpsh[f_ * 4 + rp_] = pk2(cc0, cc1);
            out[base0]      = cc0;
            out[base0 + TF] = cc1;
            #pragma unroll
            for (int off = 16; off; off >>= 1) {
                s1 += __shfl_xor_sync(0xffffffffu, s1, off);
                s2 += __shfl_xor_sync(0xffffffffu, s2, off);
                s3 += __shfl_xor_sync(0xffffffffu, s3, off);
                sd += __shfl_xor_sync(0xffffffffu, sd, off);
            }
            if (lane == 0) {
                red[wid * 4 + 0] = s1; red[wid * 4 + 1] = s2;
                red[wid * 4 + 2] = s3; red[wid * 4 + 3] = sd;
            }
        }
        __syncthreads();

        // ---------- phase 4 (all 512): gates GEMV, gate-split ----------
        if (tid < 4) {
            float s = 0.0f;
            #pragma unroll
            for (int w = 0; w < 8; ++w) s += red[w * 4 + tid];
            g_part[(t * NCTA + bid) * 4 + tid] = s;
        }
        u64 accA[4], accB[4];
        #pragma unroll
        for (int rp = 0; rp < 4; ++rp) { accA[rp] = dup2(bga); accB[rp] = dup2(bgb); }
        {
            for (int kb = 0; kb < KT / 2; kb += PREF) {
                #pragma unroll
                for (int i = 0; i < PREF; ++i) {
                    const int kp = kb + i;
                    const uint2 w2 = buf[i];
                    buf[i] = wp[(kp + PREF) * 512];          // pad rows keep in-bounds
                    #pragma unroll
                    for (int s = 0; s < 2; ++s) {
                        const unsigned int w = s ? w2.y : w2.x;
                        const float fa = __uint_as_float(w << 16);
                        const float fb = __uint_as_float(w & 0xffff0000u);
                        const u64 wa = dup2(fa), wb = dup2(fb);
                        const ulonglong2* vp2 = (const ulonglong2*)(vpsh + (2 * kp + s) * 4);
                        const ulonglong2 v01 = vp2[0];
                        const ulonglong2 v23 = vp2[1];
                        accA[0] = ffma2(v01.x, wa, accA[0]);  accB[0] = ffma2(v01.x, wb, accB[0]);
                        accA[1] = ffma2(v01.y, wa, accA[1]);  accB[1] = ffma2(v01.y, wb, accB[1]);
                        accA[2] = ffma2(v23.x, wa, accA[2]);  accB[2] = ffma2(v23.x, wb, accB[2]);
                        accA[3] = ffma2(v23.y, wa, accA[3]);  accB[3] = ffma2(v23.y, wb, accB[3]);
                    }
                }
            }
        }
        // gate exchange: half0 exports (i,f) for rp2,3 ; half1 exports (g,o) for rp0,1
        if (half == 0) {
            #pragma unroll
            for (int s = 0; s < 2; ++s) {
                gsh[(s * 2 + 0) * 256 + jj] = accA[2 + s];   // i, rp=2+s
                gsh[(s * 2 + 1) * 256 + jj] = accB[2 + s];   // f, rp=2+s
            }
        } else {
            #pragma unroll
            for (int s = 0; s < 2; ++s) {
                gsh[1024 + (s * 2 + 0) * 256 + jj] = accA[s];   // g, rp=s
                gsh[1024 + (s * 2 + 1) * 256 + jj] = accB[s];   // o, rp=s
            }
        }
        __syncthreads();

        // ---------- phase 5 (all 512, rp-split): LSTM update ----------
        {
            #pragma unroll
            for (int s = 0; s < 2; ++s) {
                const int rp = half * 2 + s;
                u64 pi, pf, pg, po;
                if (half == 0) {
                    pi = accA[rp]; pf = accB[rp];
                    pg = gsh[1024 + (s * 2 + 0) * 256 + jj];
                    po = gsh[1024 + (s * 2 + 1) * 256 + jj];
                } else {
                    pg = accA[rp]; po = accB[rp];
                    pi = gsh[(s * 2 + 0) * 256 + jj];
                    pf = gsh[(s * 2 + 1) * 256 + jj];
                }
                float i0, i1, ff0, ff1, g0, g1, o0, o1;
                upk2(pi, i0, i1);  upk2(pf, ff0, ff1);
                upk2(pg, g0, g1);  upk2(po, o0, o1);
                float c0, c1; upk2(cpsh[rp * Hd + jj], c0, c1);
                c0 = sigm(ff0) * c0 + sigm(i0) * ftanh(g0);
                c1 = sigm(ff1) * c1 + sigm(i1) * ftanh(g1);
                const float h0 = sigm(o0) * ftanh(c0);
                const float h1 = sigm(o1) * ftanh(c1);
                cpsh[rp * Hd + jj] = pk2(c0, c1);
                const u64 hv = pk2(h0, h1);
                vpsh[(128 + jj) * 4 + rp] = hv;
                hsh2[rp * 256 + jj] = hv;
            }
        }
        // ---------- fused P0(t+1) on tid<256 ----------
        if (tid < 256 && t < Tt - 1) {
            base0 += Fd;
            x0 = X[base0];  x1 = X[base0 + TF];
            m0 = MM[base0]; m1 = MM[base0 + TF];
            const float d0 = DD[base0], d1 = DD[base0 + TF];
            dpsh[rp_ * 64 + f_] = pk2(d0, d1);
            vpsh[(64 + f_) * 4 + rp_] = pk2(m0, m1);
            const float ga = __expf(-fmaxf(fmaf(d0, my_wdx, my_bdx), 0.0f));
            const float gb = __expf(-fmaxf(fmaf(d1, my_wdx, my_bdx), 0.0f));
            gxsh[rp_ * 64 + f_] = pk2(ga, gb);
        }
        __syncthreads();
    }
}

// ---------------------------------------------------------------------------
// Finalize: deterministic reduction of per-step loss partials
// ---------------------------------------------------------------------------
__global__ void rits_finalize(float* __restrict__ out) {
    const int tid = threadIdx.x, lane = tid & 31, wid = tid >> 5;
    __shared__ float wr[4][4];
    float rec_mae = 0.0f, rec_loss = 0.0f;
    for (int t = 0; t < Tt; ++t) {
        const float* p = g_part + (t * NCTA + tid) * 4;
        float v0 = p[0], v1 = p[1], v2 = p[2], v3 = p[3];
        #pragma unroll
        for (int off = 16; off; off >>= 1) {
            v0 += __shfl_xor_sync(0xffffffffu, v0, off);
            v1 += __shfl_xor_sync(0xffffffffu, v1, off);
            v2 += __shfl_xor_sync(0xffffffffu, v2, off);
            v3 += __shfl_xor_sync(0xffffffffu, v3, off);
        }
        if (lane == 0) { wr[wid][0] = v0; wr[wid][1] = v1; wr[wid][2] = v2; wr[wid][3] = v3; }
        __syncthreads();
        if (tid == 0) {
            float n1 = 0, n2 = 0, n3 = 0, dd = 0;
            #pragma unroll
            for (int w = 0; w < 4; ++w) { n1 += wr[w][0]; n2 += wr[w][1]; n3 += wr[w][2]; dd += wr[w][3]; }
            const float inv = 1.0f / (dd + 1e-9f);
            const float mae1 = n1 * inv, mae2 = n2 * inv, mae3 = n3 * inv;
            rec_mae  += mae3;
            rec_loss += mae1 + mae2 + (float)(Tt - t) * mae3;
        }
        __syncthreads();
    }
    if (tid == 0) {
        out[BTF]     = rec_mae / (float)Tt;
        out[BTF + 1] = rec_loss / (float)(Tt * 3);
    }
}

extern "C" void kernel_launch(void* const* d_in, const int* in_sizes, int n_in,
                              void* d_out, int out_size) {
    (void)in_sizes; (void)n_in; (void)out_size;
    const float* X     = (const float*)d_in[0];
    const float* MM    = (const float*)d_in[1];
    const float* DD    = (const float*)d_in[2];
    const float* Wdh   = (const float*)d_in[3];
    const float* bdh   = (const float*)d_in[4];
    const float* Wdx   = (const float*)d_in[5];
    const float* bdx   = (const float*)d_in[6];
    const float* Whist = (const float*)d_in[7];
    const float* bhist = (const float*)d_in[8];
    const float* Wfeat = (const float*)d_in[9];
    const float* bfeat = (const float*)d_in[10];
    const float* Wcomb = (const float*)d_in[11];
    const float* bcomb = (const float*)d_in[12];
    const float* Wih   = (const float*)d_in[13];
    const float* bih   = (const float*)d_in[14];
    const float* Whh   = (const float*)d_in[15];
    const float* bhh   = (const float*)d_in[16];
    float* out = (float*)d_out;

    cudaFuncSetAttribute(rits_main, cudaFuncAttributeMaxDynamicSharedMemorySize, SMEM_BYTES);

    rits_prep<<<2 * KPP, 256>>>(Wih, Whh);
    rits_main<<<NCTA, NTH, SMEM_BYTES>>>(X, MM, DD, Wdh, bdh, Wdx, bdx,
                                         Whist, bhist, Wfeat, bfeat,
                                         Wcomb, bcomb, bih, bhh, out);
    rits_finalize<<<1, 128>>>(out);
}

// round 16
// speedup vs baseline: 1.0723x; 1.0723x over previous
#include <cuda_runtime.h>
#include <cuda_bf16.h>
#include <math.h>

#define Bsz 1024
#define Tt  100
#define Fd  64
#define Hd  256
#define KT  384            // gates K: 64 (c_c) + 64 (m) + 256 (h)
#define KPP 200            // padded k-pairs (192 used + 8 pad for prefetch)
#define NCTA 128
#define NTH  512
#define PREF 8             // prefetch depth in k-pairs (16 k lookahead)
#define TF   (Tt*Fd)
#define BTF  (Bsz*Tt*Fd)

// uint2 at [(kp*2+half)*256 + jj]: .x = k=2kp, .y = k=2kp+1
// each uint = bf16x2(gateA, gateB); half0 -> (i,f), half1 -> (g,o)
static __device__ uint2 g_W2[KPP * 2 * 256];
static __device__ float g_part[Tt * NCTA * 4];

typedef unsigned long long u64;

__device__ __forceinline__ u64 pk2(float lo, float hi) {
    u64 r; asm("mov.b64 %0,{%1,%2};" : "=l"(r) : "f"(lo), "f"(hi)); return r;
}
__device__ __forceinline__ void upk2(u64 v, float& lo, float& hi) {
    asm("mov.b64 {%0,%1},%2;" : "=f"(lo), "=f"(hi) : "l"(v));
}
__device__ __forceinline__ u64 dup2(float w) {
    u64 r; asm("mov.b64 %0,{%1,%1};" : "=l"(r) : "f"(w)); return r;
}
__device__ __forceinline__ u64 ffma2(u64 a, u64 b, u64 c) {
    u64 d; asm("fma.rn.f32x2 %0,%1,%2,%3;" : "=l"(d) : "l"(a), "l"(b), "l"(c)); return d;
}
__device__ __forceinline__ u64 add2(u64 a, u64 b) {
    u64 d; asm("add.rn.f32x2 %0,%1,%2;" : "=l"(d) : "l"(a), "l"(b)); return d;
}
// sigmoid(x) = 0.5*tanh(0.5x)+0.5 using HW tanh (1 MUFU, no divide)
// verified: rel_err unchanged vs divide-based form (R13 9.533e-5 / R14 9.533e-5)
__device__ __forceinline__ float sigm(float x) {
    float y; asm("tanh.approx.f32 %0, %1;" : "=f"(y) : "f"(0.5f * x));
    return fmaf(0.5f, y, 0.5f);
}
// exp-based tanh for g/c path (precision-critical)
__device__ __forceinline__ float ftanh(float x) {
    x = fminf(fmaxf(x, -15.0f), 15.0f);
    const float e = __expf(2.0f * x);
    return __fdividef(e - 1.0f, e + 1.0f);
}

// SMEM layout (bytes)
#define OFF_VP     0        // u64[384][4]  v = [c_c | m | h], interleaved [k][rp]
#define OFF_CP     12288    // u64[4][256]  LSTM cell state
#define OFF_DP     20480    // u64[4][64]   deltas; reused as alpha-preact after P2
#define OFF_GX     22528    // u64[4][64]   gamma_x
#define OFF_XC     24576    // u64[4][64]   x_c
#define OFF_GS     26624    // u64[8][256]  g/o gate preacts [rp*2+g][j]
#define OFF_H2     43008    // u64[4][256]  h duplicate, [rp][j] contiguous
#define OFF_WDH    51200    // float[64][256]   W_dh^T  [k][j]
#define OFF_WHP    116736   // float2[128][64]  W_hist pairs: [j/2][f] = (W[j],W[j+1])
#define OFF_WFP    182272   // float2[32][64]   W_feat pairs: [k/2][f]
#define OFF_WCP    198656   // uint[64][64]     W_comb bf16x2: [k][f] = (W[f][k], W[f][64+k])
#define OFF_BDH    215040   // float[256]
#define OFF_SM     216064   // float[320]: bdx|bhist|bfeat|bcomb|wdx_diag
#define OFF_RED    217344   // float[8][4]
#define SMEM_BYTES 217472

// ---------------------------------------------------------------------------
// Prep: pack fused transposed gate weights to bf16 pairs, k-paired layout.
// ---------------------------------------------------------------------------
__global__ void rits_prep(const float* __restrict__ Wih, const float* __restrict__ Whh) {
    const int k = blockIdx.x;          // 0..2*KPP-1
    const int j = threadIdx.x;
    float w[4];
    #pragma unroll
    for (int ty = 0; ty < 4; ++ty) {
        float v = 0.0f;
        if (k < KT)
            v = (k < 128) ? Wih[(ty * 256 + j) * 128 + k]
                          : Whh[(ty * 256 + j) * 256 + (k - 128)];
        w[ty] = v;
    }
    __nv_bfloat162 p0 = __floats2bfloat162_rn(w[0], w[1]);   // i (lo), f (hi)
    __nv_bfloat162 p1 = __floats2bfloat162_rn(w[2], w[3]);   // g (lo), o (hi)
    unsigned int* base = (unsigned int*)g_W2;
    const int kp = k >> 1, sub = k & 1;
    base[(((kp * 2 + 0) * 256) + j) * 2 + sub] = *(unsigned int*)&p0;
    base[(((kp * 2 + 1) * 256) + j) * 2 + sub] = *(unsigned int*)&p1;
}

// ---------------------------------------------------------------------------
// Main persistent kernel: 128 CTAs x 8 rows x 100 steps, no grid sync.
// ---------------------------------------------------------------------------
__global__ void __launch_bounds__(NTH, 1)
rits_main(const float* __restrict__ X,   const float* __restrict__ MM,
          const float* __restrict__ DD,
          const float* __restrict__ Wdh, const float* __restrict__ bdh,
          const float* __restrict__ Wdx, const float* __restrict__ bdx,
          const float* __restrict__ Whist, const float* __restrict__ bhist,
          const float* __restrict__ Wfeat, const float* __restrict__ bfeat,
          const float* __restrict__ Wcomb, const float* __restrict__ bcomb,
          const float* __restrict__ bih, const float* __restrict__ bhh,
          float* __restrict__ out)
{
    extern __shared__ char sm[];
    u64*    vpsh   = (u64*)(sm + OFF_VP);     // [k][rp]
    u64*    cpsh   = (u64*)(sm + OFF_CP);     // [rp][j]
    u64*    dpsh   = (u64*)(sm + OFF_DP);     // [rp][f]; later alpha-preact
    u64*    gxsh   = (u64*)(sm + OFF_GX);     // [rp][f]
    u64*    xcsh   = (u64*)(sm + OFF_XC);     // [rp][f]
    u64*    gsh    = (u64*)(sm + OFF_GS);     // [rp*2+g][j]
    u64*    hsh2   = (u64*)(sm + OFF_H2);     // [rp][j]
    float*  sWdhT  = (float*)(sm + OFF_WDH);
    float2* sWhP   = (float2*)(sm + OFF_WHP);
    float2* sWfP   = (float2*)(sm + OFF_WFP);
    unsigned int* sWcP = (unsigned int*)(sm + OFF_WCP);
    float*  sbdh   = (float*)(sm + OFF_BDH);
    float*  ssm    = (float*)(sm + OFF_SM);
    float*  red    = (float*)(sm + OFF_RED);

    const int tid  = threadIdx.x;
    const int bid  = blockIdx.x;
    const int f_   = tid & 63;
    const int rp_  = (tid >> 6) & 3;
    const int wid  = tid >> 5;
    const int lane = tid & 31;
    const int jj   = tid & 255;
    const int half = tid >> 8;              // 0: gates i,f ; 1: gates g,o

    // ---- one-time weight staging ----
    for (int idx = tid; idx < Hd * Fd; idx += NTH) {        // W_dh [H][F] -> [k][j]
        int j = idx / Fd, k = idx % Fd;
        sWdhT[k * Hd + j] = Wdh[idx];
    }
    for (int idx = tid; idx < Fd * Hd; idx += NTH) {        // W_hist [F][H] -> pairs [j/2][f]
        int f = idx / Hd, j = idx % Hd;
        ((float*)sWhP)[((j >> 1) * 64 + f) * 2 + (j & 1)] = Whist[idx];
    }
    for (int idx = tid; idx < Fd * Fd; idx += NTH) {        // W_feat masked -> pairs [k/2][f]
        int f = idx / Fd, k = idx % Fd;
        ((float*)sWfP)[((k >> 1) * 64 + f) * 2 + (k & 1)] = (f == k) ? 0.0f : Wfeat[idx];
    }
    for (int idx = tid; idx < 64 * 64; idx += NTH) {        // W_comb -> bf16x2 [k][f]
        int f = idx >> 6, k = idx & 63;
        __nv_bfloat162 p = __floats2bfloat162_rn(Wcomb[f * 128 + k], Wcomb[f * 128 + 64 + k]);
        sWcP[k * 64 + f] = *(unsigned int*)&p;
    }
    for (int idx = tid; idx < Hd; idx += NTH) sbdh[idx] = bdh[idx];
    for (int idx = tid; idx < Fd; idx += NTH) {
        ssm[idx]       = bdx[idx];
        ssm[64 + idx]  = bhist[idx];
        ssm[128 + idx] = bfeat[idx];
        ssm[192 + idx] = bcomb[idx];
        ssm[256 + idx] = Wdx[idx * Fd + idx];
    }
    for (int idx = tid; idx < KT * 4; idx += NTH) vpsh[idx] = 0ULL;
    for (int idx = tid; idx < 4 * Hd; idx += NTH) { cpsh[idx] = 0ULL; hsh2[idx] = 0ULL; }
    __syncthreads();

    const float my_bdh   = sbdh[jj];
    const float my_bdx   = ssm[f_];
    const float my_bhist = ssm[64 + f_];
    const float my_bfeat = ssm[128 + f_];
    const float my_bcomb = ssm[192 + f_];
    const float my_wdx   = ssm[256 + f_];
    const float bga = bih[(half * 2 + 0) * 256 + jj] + bhh[(half * 2 + 0) * 256 + jj];
    const float bgb = bih[(half * 2 + 1) * 256 + jj] + bhh[(half * 2 + 1) * 256 + jj];

    long base0 = ((long)(bid * 8 + rp_ * 2)) * TF + f_;   // row-pair base (tid<256 active)
    float x0 = 0, x1 = 0, m0 = 0, m1 = 0;

    // ---------- prologue P0 (t=0) ----------
    if (tid < 256) {
        x0 = X[base0];  x1 = X[base0 + TF];
        m0 = MM[base0]; m1 = MM[base0 + TF];
        const float d0 = DD[base0], d1 = DD[base0 + TF];
        dpsh[rp_ * 64 + f_] = pk2(d0, d1);
        vpsh[(64 + f_) * 4 + rp_] = pk2(m0, m1);
        const float g0 = __expf(-fmaxf(fmaf(d0, my_wdx, my_bdx), 0.0f));
        const float g1 = __expf(-fmaxf(fmaf(d1, my_wdx, my_bdx), 0.0f));
        gxsh[rp_ * 64 + f_] = pk2(g0, g1);
    }
    __syncthreads();

    const uint2* wp = g_W2 + half * 256 + jj;   // stride 512 uint2 per k-pair

    for (int t = 0; t < Tt; ++t) {
        // ---- prefetch gate-weight pipeline (static data; overlaps P1-P3) ----
        uint2 buf[PREF];
        #pragma unroll
        for (int p = 0; p < PREF; ++p) buf[p] = wp[p * 512];

        // ---------- phase 1 (all 512): gamma_h, h *= gamma_h ----------
        {
            const int rb = half * 2;
            u64 a0 = 0ULL, a1 = 0ULL, a2 = 0ULL, a3 = 0ULL;
            #pragma unroll 8
            for (int k = 0; k < Fd; k += 2) {
                const u64 w0 = dup2(sWdhT[k * Hd + jj]);
                const u64 w1 = dup2(sWdhT[(k + 1) * Hd + jj]);
                const ulonglong2 dA = *(const ulonglong2*)(dpsh + rb * 64 + k);
                const ulonglong2 dB = *(const ulonglong2*)(dpsh + (rb + 1) * 64 + k);
                a0 = ffma2(dA.x, w0, a0);  a1 = ffma2(dA.y, w1, a1);
                a2 = ffma2(dB.x, w0, a2);  a3 = ffma2(dB.y, w1, a3);
            }
            const u64 sA = add2(a0, a1), sB = add2(a2, a3);
            float l0, h0v, l1, h1v;
            upk2(sA, l0, h0v);
            upk2(sB, l1, h1v);
            const float ga = __expf(-fmaxf(l0  + my_bdh, 0.0f));
            const float gb = __expf(-fmaxf(h0v + my_bdh, 0.0f));
            const float gc = __expf(-fmaxf(l1  + my_bdh, 0.0f));
            const float gd = __expf(-fmaxf(h1v + my_bdh, 0.0f));
            ulonglong2* hp = (ulonglong2*)(vpsh + (128 + jj) * 4 + rb);
            ulonglong2 hv = *hp;
            float ha, hb, hc, hd;
            upk2(hv.x, ha, hb);  upk2(hv.y, hc, hd);
            hv.x = pk2(ha * ga, hb * gb);
            hv.y = pk2(hc * gc, hd * gd);
            *hp = hv;
            hsh2[rb * 256 + jj]       = hv.x;
            hsh2[(rb + 1) * 256 + jj] = hv.y;
        }
        __syncthreads();

        // ---------- phase 2: half0 -> x_h GEMV; half1 -> alpha GEMV ----------
        float xh0 = 0, xh1 = 0, s1 = 0;
        if (half == 0) {
            u64 acc0 = dup2(my_bhist), acc1 = 0ULL, acc2 = 0ULL, acc3 = 0ULL;
            #pragma unroll 8
            for (int jp = 0; jp < 128; jp += 2) {
                const ulonglong2 vA = *(const ulonglong2*)(hsh2 + rp_ * 256 + 2 * jp);
                const float2 wA = sWhP[jp * 64 + f_];
                const ulonglong2 vB = *(const ulonglong2*)(hsh2 + rp_ * 256 + 2 * jp + 2);
                const float2 wB = sWhP[(jp + 1) * 64 + f_];
                acc0 = ffma2(vA.x, dup2(wA.x), acc0);
                acc1 = ffma2(vA.y, dup2(wA.y), acc1);
                acc2 = ffma2(vB.x, dup2(wB.x), acc2);
                acc3 = ffma2(vB.y, dup2(wB.y), acc3);
            }
            const u64 acc = add2(add2(acc0, acc1), add2(acc2, acc3));
            upk2(acc, xh0, xh1);
            const float xc0 = m0 * x0 + (1.0f - m0) * xh0;
            const float xc1 = m1 * x1 + (1.0f - m1) * xh1;
            xcsh[rp_ * 64 + f_] = pk2(xc0, xc1);
            s1 = fabsf(xh0 - x0) * m0 + fabsf(xh1 - x1) * m1;
        } else {
            // alpha preact = [gamma_x, m] @ W_comb^T + b  (bf16 packed weights)
            u64 a0a = dup2(my_bcomb), a1a = 0ULL, a2a = 0ULL, a3a = 0ULL;
            #pragma unroll 8
            for (int kp = 0; kp < 32; ++kp) {
                const ulonglong2 g2 = *(const ulonglong2*)(gxsh + rp_ * 64 + 2 * kp);
                const unsigned int u0 = sWcP[(2 * kp) * 64 + f_];
                const unsigned int u1 = sWcP[(2 * kp + 1) * 64 + f_];
                a0a = ffma2(g2.x, dup2(__uint_as_float(u0 << 16)), a0a);
                a1a = ffma2(g2.y, dup2(__uint_as_float(u1 << 16)), a1a);
                a2a = ffma2(vpsh[(64 + 2 * kp) * 4 + rp_],
                            dup2(__uint_as_float(u0 & 0xffff0000u)), a2a);
                a3a = ffma2(vpsh[(64 + 2 * kp + 1) * 4 + rp_],
                            dup2(__uint_as_float(u1 & 0xffff0000u)), a3a);
            }
            dpsh[rp_ * 64 + f_] = add2(add2(a0a, a1a), add2(a2a, a3a));
        }
        __syncthreads();

        // ---------- phase 3 (tid<256): z_h, c_h, c_c, out, losses ----------
        if (tid < 256) {
            u64 z0a = dup2(my_bfeat), z1a = 0ULL;
            #pragma unroll 8
            for (int kp = 0; kp < 32; ++kp) {
                const ulonglong2 xv = *(const ulonglong2*)(xcsh + rp_ * 64 + 2 * kp);
                const float2 w2 = sWfP[kp * 64 + f_];
                z0a = ffma2(xv.x, dup2(w2.x), z0a);
                z1a = ffma2(xv.y, dup2(w2.y), z1a);
            }
            float z0, z1, al0, al1;
            upk2(add2(z0a, z1a), z0, z1);
            upk2(dpsh[rp_ * 64 + f_], al0, al1);
            al0 = sigm(al0); al1 = sigm(al1);
            const float ch0 = al0 * z0 + (1.0f - al0) * xh0;
            const float ch1 = al1 * z1 + (1.0f - al1) * xh1;
            float s2 = fabsf(z0 - x0) * m0 + fabsf(z1 - x1) * m1;
            float s3 = fabsf(ch0 - x0) * m0 + fabsf(ch1 - x1) * m1;
            float sd = m0 + m1;
            const float cc0 = m0 * x0 + (1.0f - m0) * ch0;    // imputed element
            const float cc1 = m1 * x1 + (1.0f - m1) * ch1;
            vpsh[f_ * 4 + rp_] = pk2(cc0, cc1);
            out[base0]      = cc0;
            out[base0 + TF] = cc1;
            #pragma unroll
            for (int off = 16; off; off >>= 1) {
                s1 += __shfl_xor_sync(0xffffffffu, s1, off);
                s2 += __shfl_xor_sync(0xffffffffu, s2, off);
                s3 += __shfl_xor_sync(0xffffffffu, s3, off);
                sd += __shfl_xor_sync(0xffffffffu, sd, off);
            }
            if (lane == 0) {
                red[wid * 4 + 0] = s1; red[wid * 4 + 1] = s2;
                red[wid * 4 + 2] = s3; red[wid * 4 + 3] = sd;
            }
        }
        __syncthreads();

        // ---------- phase 4 (all 512): gates GEMV, gate-split ----------
        if (tid < 4) {
            float s = 0.0f;
            #pragma unroll
            for (int w = 0; w < 8; ++w) s += red[w * 4 + tid];
            g_part[(t * NCTA + bid) * 4 + tid] = s;
        }
        // hoisted next-step input loads: issued before the long GEMV so the
        // L2/DRAM latency is hidden behind ~12K cycles of FFMA2 work
        float xn0 = 0, xn1 = 0, mn0 = 0, mn1 = 0, dn0 = 0, dn1 = 0;
        const long base1 = base0 + Fd;
        if (tid < 256 && t < Tt - 1) {
            xn0 = X[base1];  xn1 = X[base1 + TF];
            mn0 = MM[base1]; mn1 = MM[base1 + TF];
            dn0 = DD[base1]; dn1 = DD[base1 + TF];
        }
        u64 accA[4], accB[4];
        #pragma unroll
        for (int rp = 0; rp < 4; ++rp) { accA[rp] = dup2(bga); accB[rp] = dup2(bgb); }
        {
            for (int kb = 0; kb < KT / 2; kb += PREF) {
                #pragma unroll
                for (int i = 0; i < PREF; ++i) {
                    const int kp = kb + i;
                    const uint2 w2 = buf[i];
                    buf[i] = wp[(kp + PREF) * 512];          // pad rows keep in-bounds
                    #pragma unroll
                    for (int s = 0; s < 2; ++s) {
                        const unsigned int w = s ? w2.y : w2.x;
                        const float fa = __uint_as_float(w << 16);
                        const float fb = __uint_as_float(w & 0xffff0000u);
                        const u64 wa = dup2(fa), wb = dup2(fb);
                        const ulonglong2* vp2 = (const ulonglong2*)(vpsh + (2 * kp + s) * 4);
                        const ulonglong2 v01 = vp2[0];
                        const ulonglong2 v23 = vp2[1];
                        accA[0] = ffma2(v01.x, wa, accA[0]);  accB[0] = ffma2(v01.x, wb, accB[0]);
                        accA[1] = ffma2(v01.y, wa, accA[1]);  accB[1] = ffma2(v01.y, wb, accB[1]);
                        accA[2] = ffma2(v23.x, wa, accA[2]);  accB[2] = ffma2(v23.x, wb, accB[2]);
                        accA[3] = ffma2(v23.y, wa, accA[3]);  accB[3] = ffma2(v23.y, wb, accB[3]);
                    }
                }
            }
        }
        if (half == 1) {   // export g,o preacts
            #pragma unroll
            for (int rp = 0; rp < 4; ++rp) {
                gsh[(rp * 2 + 0) * 256 + jj] = accA[rp];   // g
                gsh[(rp * 2 + 1) * 256 + jj] = accB[rp];   // o
            }
        }
        __syncthreads();

        // ---------- phase 5 (tid<256): LSTM update ; then fused P0(t+1) ----------
        if (tid < 256) {
            const int j = tid;
            #pragma unroll
            for (int rp = 0; rp < 4; ++rp) {
                float i0, i1, ff0, ff1, g0, g1, o0, o1;
                upk2(accA[rp], i0, i1);
                upk2(accB[rp], ff0, ff1);
                upk2(gsh[(rp * 2 + 0) * 256 + j], g0, g1);
                upk2(gsh[(rp * 2 + 1) * 256 + j], o0, o1);
                float c0, c1; upk2(cpsh[rp * Hd + j], c0, c1);
                c0 = sigm(ff0) * c0 + sigm(i0) * ftanh(g0);
                c1 = sigm(ff1) * c1 + sigm(i1) * ftanh(g1);
                const float h0 = sigm(o0) * ftanh(c0);
                const float h1 = sigm(o1) * ftanh(c1);
                cpsh[rp * Hd + j] = pk2(c0, c1);
                const u64 hv = pk2(h0, h1);
                vpsh[(128 + j) * 4 + rp] = hv;
                hsh2[rp * 256 + j] = hv;
            }
            if (t < Tt - 1) {   // fused P0 for next step (data already in registers)
                base0 = base1;
                x0 = xn0; x1 = xn1; m0 = mn0; m1 = mn1;
                dpsh[rp_ * 64 + f_] = pk2(dn0, dn1);
                vpsh[(64 + f_) * 4 + rp_] = pk2(m0, m1);
                const float ga = __expf(-fmaxf(fmaf(dn0, my_wdx, my_bdx), 0.0f));
                const float gb = __expf(-fmaxf(fmaf(dn1, my_wdx, my_bdx), 0.0f));
                gxsh[rp_ * 64 + f_] = pk2(ga, gb);
            }
        }
        __syncthreads();
    }
}

// ---------------------------------------------------------------------------
// Finalize: deterministic reduction of per-step loss partials
// ---------------------------------------------------------------------------
__global__ void rits_finalize(float* __restrict__ out) {
    const int tid = threadIdx.x, lane = tid & 31, wid = tid >> 5;
    __shared__ float wr[4][4];
    float rec_mae = 0.0f, rec_loss = 0.0f;
    for (int t = 0; t < Tt; ++t) {
        const float* p = g_part + (t * NCTA + tid) * 4;
        float v0 = p[0], v1 = p[1], v2 = p[2], v3 = p[3];
        #pragma unroll
        for (int off = 16; off; off >>= 1) {
            v0 += __shfl_xor_sync(0xffffffffu, v0, off);
            v1 += __shfl_xor_sync(0xffffffffu, v1, off);
            v2 += __shfl_xor_sync(0xffffffffu, v2, off);
            v3 += __shfl_xor_sync(0xffffffffu, v3, off);
        }
        if (lane == 0) { wr[wid][0] = v0; wr[wid][1] = v1; wr[wid][2] = v2; wr[wid][3] = v3; }
        __syncthreads();
        if (tid == 0) {
            float n1 = 0, n2 = 0, n3 = 0, dd = 0;
            #pragma unroll
            for (int w = 0; w < 4; ++w) { n1 += wr[w][0]; n2 += wr[w][1]; n3 += wr[w][2]; dd += wr[w][3]; }
            const float inv = 1.0f / (dd + 1e-9f);
            const float mae1 = n1 * inv, mae2 = n2 * inv, mae3 = n3 * inv;
            rec_mae  += mae3;
            rec_loss += mae1 + mae2 + (float)(Tt - t) * mae3;
        }
        __syncthreads();
    }
    if (tid == 0) {
        out[BTF]     = rec_mae / (float)Tt;
        out[BTF + 1] = rec_loss / (float)(Tt * 3);
    }
}

extern "C" void kernel_launch(void* const* d_in, const int* in_sizes, int n_in,
                              void* d_out, int out_size) {
    (void)in_sizes; (void)n_in; (void)out_size;
    const float* X     = (const float*)d_in[0];
    const float* MM    = (const float*)d_in[1];
    const float* DD    = (const float*)d_in[2];
    const float* Wdh   = (const float*)d_in[3];
    const float* bdh   = (const float*)d_in[4];
    const float* Wdx   = (const float*)d_in[5];
    const float* bdx   = (const float*)d_in[6];
    const float* Whist = (const float*)d_in[7];
    const float* bhist = (const float*)d_in[8];
    const float* Wfeat = (const float*)d_in[9];
    const float* bfeat = (const float*)d_in[10];
    const float* Wcomb = (const float*)d_in[11];
    const float* bcomb = (const float*)d_in[12];
    const float* Wih   = (const float*)d_in[13];
    const float* bih   = (const float*)d_in[14];
    const float* Whh   = (const float*)d_in[15];
    const float* bhh   = (const float*)d_in[16];
    float* out = (float*)d_out;

    cudaFuncSetAttribute(rits_main, cudaFuncAttributeMaxDynamicSharedMemorySize, SMEM_BYTES);

    rits_prep<<<2 * KPP, 256>>>(Wih, Whh);
    rits_main<<<NCTA, NTH, SMEM_BYTES>>>(X, MM, DD, Wdh, bdh, Wdx, bdx,
                                         Whist, bhist, Wfeat, bfeat,
                                         Wcomb, bcomb, bih, bhh, out);
    rits_finalize<<<1, 128>>>(out);
}